// round 1
// baseline (speedup 1.0000x reference)
#include <cuda_runtime.h>
#include <cstdint>
#include <cstdio>

// Problem constants (fixed by the dataset)
#define NN    50000
#define EE    800000
#define IN_F  96
#define HID_F 128
#define OUT_F 64
#define TT    8

// ---------------- static device scratch (no allocations allowed) -------------
__device__ int   g_counts[NN];
__device__ int   g_rowptr[NN + 1];
__device__ int   g_cursor[NN];
__device__ int   g_csrc[EE];
__device__ float g_cw[EE];
__device__ float g_agg1[(size_t)NN * IN_F];                 // 19.2 MB
__device__ float g_h[(size_t)TT * NN * HID_F];              // 204.8 MB
__device__ float g_p[(size_t)TT * NN * OUT_F];              // 102.4 MB

// ---------------- CSR build --------------------------------------------------
__global__ void k_zero_counts() {
    int i = blockIdx.x * blockDim.x + threadIdx.x;
    if (i < NN) g_counts[i] = 0;
}

__global__ void k_hist(const int* __restrict__ dst) {
    int e = blockIdx.x * blockDim.x + threadIdx.x;
    if (e < EE) atomicAdd(&g_counts[dst[e]], 1);
}

// single-block exclusive scan over 50000 counts
__global__ void k_scan() {
    __shared__ int sums[1024];
    int tid = threadIdx.x;
    const int chunk = (NN + 1023) / 1024;   // 49
    int start = tid * chunk; if (start > NN) start = NN;
    int end   = start + chunk; if (end > NN) end = NN;
    int s = 0;
    for (int i = start; i < end; i++) s += g_counts[i];
    sums[tid] = s;
    __syncthreads();
    for (int off = 1; off < 1024; off <<= 1) {
        int v = (tid >= off) ? sums[tid - off] : 0;
        __syncthreads();
        sums[tid] += v;
        __syncthreads();
    }
    int run = (tid == 0) ? 0 : sums[tid - 1];
    for (int i = start; i < end; i++) {
        g_rowptr[i] = run;
        g_cursor[i] = run;
        run += g_counts[i];
    }
    if (end == NN) g_rowptr[NN] = run;
}

__global__ void k_scatter(const int* __restrict__ src, const int* __restrict__ dst,
                          const float* __restrict__ ew) {
    int e = blockIdx.x * blockDim.x + threadIdx.x;
    if (e >= EE) return;
    int d = dst[e];
    int pos = atomicAdd(&g_cursor[d], 1);
    g_csrc[pos] = src[e];
    g_cw[pos]   = ew[e];
}

// ---------------- SpMM (CSR, warp per destination node) ----------------------
// agg1[n, 0:96] = sum_{e: dst=n} w_e * x[src_e, :]
__global__ void k_spmm96(const float* __restrict__ x) {
    int warp = (blockIdx.x * blockDim.x + threadIdx.x) >> 5;
    int lane = threadIdx.x & 31;
    if (warp >= NN) return;
    int r0 = g_rowptr[warp], r1 = g_rowptr[warp + 1];
    float a0 = 0.f, a1 = 0.f, a2 = 0.f;
    for (int r = r0; r < r1; r++) {
        int   s = g_csrc[r];
        float w = g_cw[r];
        const float* f = x + (size_t)s * IN_F;
        a0 += w * f[lane];
        a1 += w * f[lane + 32];
        a2 += w * f[lane + 64];
    }
    float* o = g_agg1 + (size_t)warp * IN_F;
    o[lane] = a0; o[lane + 32] = a1; o[lane + 64] = a2;
}

// out[t, n, 0:64] = sum_{e: dst=n} w_e * p_t[src_e, :]   (writes final output)
__global__ void k_spmm64(float* __restrict__ out) {
    int t    = blockIdx.y;
    int warp = (blockIdx.x * blockDim.x + threadIdx.x) >> 5;
    int lane = threadIdx.x & 31;
    if (warp >= NN) return;
    const float* p = g_p + (size_t)t * NN * OUT_F;
    int r0 = g_rowptr[warp], r1 = g_rowptr[warp + 1];
    float ax = 0.f, ay = 0.f;
    for (int r = r0; r < r1; r++) {
        int   s = g_csrc[r];
        float w = g_cw[r];
        float2 v = *(const float2*)(p + (size_t)s * OUT_F + lane * 2);
        ax += w * v.x;
        ay += w * v.y;
    }
    float2 res = make_float2(ax, ay);
    *((float2*)(out + (size_t)t * NN * OUT_F + (size_t)warp * OUT_F) + lane) = res;
}

// ---------------- batched masked GEMM ----------------------------------------
// MODE 0: C = relu(g_agg1 [N x 96]  @ (W1*mask1_t) [96 x 128]) -> g_h  (per t)
// MODE 1: C =       g_h_t [N x 128] @ (W2*mask2_t) [128 x 64]  -> g_p  (per t)
template<int K, int NCOL, int MTILE, int TM, int TN, bool RELU, int MODE>
__global__ void k_gemm(const float* __restrict__ W, const float* __restrict__ Mk) {
    constexpr int KT = 16;
    constexpr int BX = NCOL / TN;
    constexpr int BY = MTILE / TM;
    constexpr int NTHREADS = BX * BY;

    extern __shared__ float smem[];
    float* Bs = smem;                    // K * NCOL
    float* As = smem + K * NCOL;         // MTILE * (KT+1)

    int t = blockIdx.y;
    const float* A;
    float* C;
    if (MODE == 0) {
        A = g_agg1;
        C = g_h + (size_t)t * NN * HID_F;
    } else {
        A = g_h + (size_t)t * NN * HID_F;
        C = g_p + (size_t)t * NN * OUT_F;
    }
    const float* Mp = Mk + (size_t)t * K * NCOL;

    int tid = threadIdx.x;

    // stage masked weights (reused across all K iterations of the block)
    for (int i = tid; i < K * NCOL; i += NTHREADS)
        Bs[i] = W[i] * Mp[i];

    int row0 = blockIdx.x * MTILE;
    int tx = tid % BX;
    int ty = tid / BX;

    float acc[TM][TN];
    #pragma unroll
    for (int r = 0; r < TM; r++)
        #pragma unroll
        for (int c = 0; c < TN; c++)
            acc[r][c] = 0.f;

    for (int k0 = 0; k0 < K; k0 += KT) {
        __syncthreads();
        for (int e = tid; e < MTILE * KT; e += NTHREADS) {
            int i  = e / KT;
            int kk = e % KT;
            int gr = row0 + i;
            As[i * (KT + 1) + kk] = (gr < NN) ? A[(size_t)gr * K + k0 + kk] : 0.f;
        }
        __syncthreads();
        #pragma unroll
        for (int kk = 0; kk < KT; kk++) {
            float a[TM], b[TN];
            #pragma unroll
            for (int r = 0; r < TM; r++)
                a[r] = As[(ty * TM + r) * (KT + 1) + kk];
            #pragma unroll
            for (int c = 0; c < TN; c++)
                b[c] = Bs[(k0 + kk) * NCOL + tx * TN + c];
            #pragma unroll
            for (int r = 0; r < TM; r++)
                #pragma unroll
                for (int c = 0; c < TN; c++)
                    acc[r][c] += a[r] * b[c];
        }
    }

    #pragma unroll
    for (int r = 0; r < TM; r++) {
        int gr = row0 + ty * TM + r;
        if (gr < NN) {
            float* cp = C + (size_t)gr * NCOL + tx * TN;
            #pragma unroll
            for (int c = 0; c < TN; c++) {
                float v = acc[r][c];
                if (RELU) v = v > 0.f ? v : 0.f;
                cp[c] = v;
            }
        }
    }
}

// ---------------- launch ------------------------------------------------------
extern "C" void kernel_launch(void* const* d_in, const int* in_sizes, int n_in,
                              void* d_out, int out_size) {
    (void)in_sizes; (void)n_in; (void)out_size;
    const float* x   = (const float*)d_in[0];
    const float* ew  = (const float*)d_in[1];
    const float* W1  = (const float*)d_in[2];
    const float* W2  = (const float*)d_in[3];
    const float* m1  = (const float*)d_in[4];
    const float* m2  = (const float*)d_in[5];
    const int*   src = (const int*)d_in[6];
    const int*   dst = (const int*)d_in[7];
    float* out = (float*)d_out;

    // GEMM1: K=96, NCOL=128, MTILE=128, TM=TN=8 -> 256 threads
    constexpr int SMEM1 = (96 * 128 + 128 * 17) * 4;    // 57856 B
    // GEMM2: K=128, NCOL=64, MTILE=256, TM=TN=8 -> 256 threads
    constexpr int SMEM2 = (128 * 64 + 256 * 17) * 4;    // 50176 B

    cudaFuncSetAttribute((const void*)k_gemm<96, 128, 128, 8, 8, true, 0>,
                         cudaFuncAttributeMaxDynamicSharedMemorySize, SMEM1);
    cudaFuncSetAttribute((const void*)k_gemm<128, 64, 256, 8, 8, false, 1>,
                         cudaFuncAttributeMaxDynamicSharedMemorySize, SMEM2);

    // 1. CSR build
    k_zero_counts<<<(NN + 255) / 256, 256>>>();
    k_hist<<<(EE + 255) / 256, 256>>>(dst);
    k_scan<<<1, 1024>>>();
    k_scatter<<<(EE + 255) / 256, 256>>>(src, dst, ew);

    // 2. agg1 = spmm(x)   [N x 96]
    k_spmm96<<<(NN * 32 + 255) / 256, 256>>>(x);

    // 3. h_t = relu(agg1 @ (W1*m1_t))   batched over t
    dim3 g1((NN + 127) / 128, TT);
    k_gemm<96, 128, 128, 8, 8, true, 0><<<g1, 256, SMEM1>>>(W1, m1);

    // 4. p_t = h_t @ (W2*m2_t)          batched over t
    dim3 g2((NN + 255) / 256, TT);
    k_gemm<128, 64, 256, 8, 8, false, 1><<<g2, 256, SMEM2>>>(W2, m2);

    // 5. out_t = spmm(p_t)              batched over t, writes d_out directly
    dim3 g3((NN * 32 + 255) / 256, TT);
    k_spmm64<<<g3, 256>>>(out);
}

// round 3
// speedup vs baseline: 1.9580x; 1.9580x over previous
#include <cuda_runtime.h>
#include <cstdint>

// Problem constants (fixed by the dataset)
#define NN    50000
#define EE    800000
#define IN_F  96
#define HID_F 128
#define OUT_F 64
#define TT    8

// ---------------- static device scratch (no allocations allowed) -------------
__device__ int   g_counts[NN];
__device__ int   g_rowptr[NN + 1];
__device__ int   g_cursor[NN];
__device__ int   g_csrc[EE];
__device__ float g_cw[EE];
__device__ float g_agg1[(size_t)NN * IN_F];                 // 19.2 MB
__device__ float g_p[(size_t)TT * NN * OUT_F];              // 102.4 MB

// ---------------- helpers ------------------------------------------------------
__device__ __forceinline__ uint32_t f2tf32(float x) {
    uint32_t u;
    asm("cvt.rna.tf32.f32 %0, %1;" : "=r"(u) : "f"(x));
    return u;
}

// warp-level tf32 MMA (sm_80+ PTX, runs on Blackwell tensor pipes)
__device__ __forceinline__ void mma_tf32(float d[4],
                                         uint32_t a0, uint32_t a1, uint32_t a2, uint32_t a3,
                                         uint32_t b0, uint32_t b1) {
    asm volatile("mma.sync.aligned.m16n8k8.row.col.f32.tf32.tf32.f32 "
        "{%0,%1,%2,%3}, {%4,%5,%6,%7}, {%8,%9}, {%0,%1,%2,%3};"
        : "+f"(d[0]), "+f"(d[1]), "+f"(d[2]), "+f"(d[3])
        : "r"(a0), "r"(a1), "r"(a2), "r"(a3), "r"(b0), "r"(b1));
}

// ---------------- CSR build --------------------------------------------------
__global__ void k_zero_counts() {
    int i = blockIdx.x * blockDim.x + threadIdx.x;
    if (i < NN) g_counts[i] = 0;
}
__global__ void k_hist(const int* __restrict__ dst) {
    int e = blockIdx.x * blockDim.x + threadIdx.x;
    if (e < EE) atomicAdd(&g_counts[dst[e]], 1);
}
__global__ void k_scan() {
    __shared__ int sums[1024];
    int tid = threadIdx.x;
    const int chunk = (NN + 1023) / 1024;
    int start = tid * chunk; if (start > NN) start = NN;
    int end   = start + chunk; if (end > NN) end = NN;
    int s = 0;
    for (int i = start; i < end; i++) s += g_counts[i];
    sums[tid] = s;
    __syncthreads();
    for (int off = 1; off < 1024; off <<= 1) {
        int v = (tid >= off) ? sums[tid - off] : 0;
        __syncthreads();
        sums[tid] += v;
        __syncthreads();
    }
    int run = (tid == 0) ? 0 : sums[tid - 1];
    for (int i = start; i < end; i++) {
        g_rowptr[i] = run;
        g_cursor[i] = run;
        run += g_counts[i];
    }
    if (end == NN) g_rowptr[NN] = run;
}
__global__ void k_scatter(const int* __restrict__ src, const int* __restrict__ dst,
                          const float* __restrict__ ew) {
    int e = blockIdx.x * blockDim.x + threadIdx.x;
    if (e >= EE) return;
    int d = dst[e];
    int pos = atomicAdd(&g_cursor[d], 1);
    g_csrc[pos] = src[e];
    g_cw[pos]   = ew[e];
}

// ---------------- SpMM (CSR, warp per destination node) ----------------------
__global__ void k_spmm96(const float* __restrict__ x) {
    int warp = (blockIdx.x * blockDim.x + threadIdx.x) >> 5;
    int lane = threadIdx.x & 31;
    if (warp >= NN) return;
    int r0 = g_rowptr[warp], r1 = g_rowptr[warp + 1];
    float a0 = 0.f, a1 = 0.f, a2 = 0.f;
    for (int r = r0; r < r1; r++) {
        int   s = g_csrc[r];
        float w = g_cw[r];
        const float* f = x + (size_t)s * IN_F;
        a0 += w * f[lane];
        a1 += w * f[lane + 32];
        a2 += w * f[lane + 64];
    }
    float* o = g_agg1 + (size_t)warp * IN_F;
    o[lane] = a0; o[lane + 32] = a1; o[lane + 64] = a2;
}

__global__ void k_spmm64(float* __restrict__ out) {
    int t    = blockIdx.y;
    int warp = (blockIdx.x * blockDim.x + threadIdx.x) >> 5;
    int lane = threadIdx.x & 31;
    if (warp >= NN) return;
    const float* p = g_p + (size_t)t * NN * OUT_F;
    int r0 = g_rowptr[warp], r1 = g_rowptr[warp + 1];
    float ax = 0.f, ay = 0.f;
    for (int r = r0; r < r1; r++) {
        int   s = g_csrc[r];
        float w = g_cw[r];
        float2 v = *(const float2*)(p + (size_t)s * OUT_F + lane * 2);
        ax += w * v.x;
        ay += w * v.y;
    }
    float2 res = make_float2(ax, ay);
    *((float2*)(out + (size_t)t * NN * OUT_F + (size_t)warp * OUT_F) + lane) = res;
}

// ---------------- fused tf32 mma.sync GEMM ------------------------------------
// p_t[tile] = relu(agg1[tile] @ (W1*m1_t)) @ (W2*m2_t)
// CTA = 128 rows x one t. 8 warps, warp w owns rows [16w, 16w+16).
// smem (uint32 words), padded strides chosen for conflict-free fragment access:
//   A  at 0      : 128 x 96,  lda  = 100  (12800 w)  -- dead after GEMM1
//   B1 at 12800  : 96  x 128, ldb1 = 136  (13056 w)  -- dead after GEMM1
//   H  at 0      : 128 x 128, ldh  = 132  (16896 w)  -- overlaps A/B1
//   B2 at 25856  : 128 x 64,  ldb2 = 72   ( 9216 w)
#define OFF_A   0
#define LDA     100
#define OFF_B1  12800
#define LDB1    136
#define OFF_H   0
#define LDH     132
#define OFF_B2  25856
#define LDB2    72
#define FUSED_WORDS (OFF_B2 + 128 * LDB2)          // 35072 words
#define FUSED_SMEM  (FUSED_WORDS * 4)              // 140288 bytes

__global__ void __launch_bounds__(256)
k_fused_gemm(const float* __restrict__ W1, const float* __restrict__ W2,
             const float* __restrict__ M1, const float* __restrict__ M2) {
    extern __shared__ uint32_t sm[];
    const int tid  = threadIdx.x;
    const int wid  = tid >> 5;
    const int lane = tid & 31;
    const int gid  = lane >> 2;      // 0..7
    const int tig  = lane & 3;       // 0..3
    const int row0 = blockIdx.x * 128;
    const int t    = blockIdx.y;

    // ---- stage A tile (tf32), zero-fill OOB rows
    #pragma unroll
    for (int e = tid; e < 128 * 96; e += 256) {
        int r = e / 96, k = e % 96;
        int gr = row0 + r;
        float v = (gr < NN) ? g_agg1[(size_t)gr * 96 + k] : 0.f;
        sm[OFF_A + r * LDA + k] = f2tf32(v);
    }
    // ---- stage B1_t = W1 * M1_t  (96 x 128, [k][n])
    {
        const float* m1p = M1 + (size_t)t * 96 * 128;
        #pragma unroll
        for (int e = tid; e < 96 * 128; e += 256) {
            int k = e >> 7, n = e & 127;
            sm[OFF_B1 + k * LDB1 + n] = f2tf32(W1[e] * m1p[e]);
        }
    }
    // ---- stage B2_t = W2 * M2_t  (128 x 64, [k][n])
    {
        const float* m2p = M2 + (size_t)t * 128 * 64;
        #pragma unroll
        for (int e = tid; e < 128 * 64; e += 256) {
            int k = e >> 6, n = e & 63;
            sm[OFF_B2 + k * LDB2 + n] = f2tf32(W2[e] * m2p[e]);
        }
    }
    __syncthreads();

    const int r0 = wid * 16;

    // ================= GEMM1: h[128,128] = A[128,96] @ B1 ====================
    float acc1[16][4];
    #pragma unroll
    for (int j = 0; j < 16; j++)
        #pragma unroll
        for (int i = 0; i < 4; i++) acc1[j][i] = 0.f;

    #pragma unroll
    for (int kb = 0; kb < 12; kb++) {
        const int k0 = kb * 8;
        uint32_t a0 = sm[OFF_A + (r0 + gid)     * LDA + k0 + tig];
        uint32_t a1 = sm[OFF_A + (r0 + gid + 8) * LDA + k0 + tig];
        uint32_t a2 = sm[OFF_A + (r0 + gid)     * LDA + k0 + tig + 4];
        uint32_t a3 = sm[OFF_A + (r0 + gid + 8) * LDA + k0 + tig + 4];
        #pragma unroll
        for (int j = 0; j < 16; j++) {
            uint32_t b0 = sm[OFF_B1 + (k0 + tig)     * LDB1 + j * 8 + gid];
            uint32_t b1 = sm[OFF_B1 + (k0 + tig + 4) * LDB1 + j * 8 + gid];
            mma_tf32(acc1[j], a0, a1, a2, a3, b0, b1);
        }
    }

    // relu + tf32-round in registers
    uint32_t hreg[16][4];
    #pragma unroll
    for (int j = 0; j < 16; j++)
        #pragma unroll
        for (int i = 0; i < 4; i++) {
            float f = acc1[j][i];
            hreg[j][i] = f2tf32(f > 0.f ? f : 0.f);
        }

    __syncthreads();   // everyone done reading A/B1 -> safe to overwrite with H

    // store h fragments: c0 -> (row, 2tig+8j), c1 -> col+1, c2/c3 -> row+8
    #pragma unroll
    for (int j = 0; j < 16; j++) {
        int cA = j * 8 + 2 * tig;
        sm[OFF_H + (r0 + gid)     * LDH + cA]     = hreg[j][0];
        sm[OFF_H + (r0 + gid)     * LDH + cA + 1] = hreg[j][1];
        sm[OFF_H + (r0 + gid + 8) * LDH + cA]     = hreg[j][2];
        sm[OFF_H + (r0 + gid + 8) * LDH + cA + 1] = hreg[j][3];
    }
    __syncthreads();

    // ================= GEMM2: p[128,64] = H[128,128] @ B2 =====================
    float acc2[8][4];
    #pragma unroll
    for (int j = 0; j < 8; j++)
        #pragma unroll
        for (int i = 0; i < 4; i++) acc2[j][i] = 0.f;

    #pragma unroll
    for (int kb = 0; kb < 16; kb++) {
        const int k0 = kb * 8;
        uint32_t a0 = sm[OFF_H + (r0 + gid)     * LDH + k0 + tig];
        uint32_t a1 = sm[OFF_H + (r0 + gid + 8) * LDH + k0 + tig];
        uint32_t a2 = sm[OFF_H + (r0 + gid)     * LDH + k0 + tig + 4];
        uint32_t a3 = sm[OFF_H + (r0 + gid + 8) * LDH + k0 + tig + 4];
        #pragma unroll
        for (int j = 0; j < 8; j++) {
            uint32_t b0 = sm[OFF_B2 + (k0 + tig)     * LDB2 + j * 8 + gid];
            uint32_t b1 = sm[OFF_B2 + (k0 + tig + 4) * LDB2 + j * 8 + gid];
            mma_tf32(acc2[j], a0, a1, a2, a3, b0, b1);
        }
    }

    // ---- epilogue: write p_t tile (float2 per fragment row)
    {
        const size_t base = (size_t)t * NN;
        int rowA = row0 + r0 + gid;
        int rowB = rowA + 8;
        if (rowA < NN) {
            float* p = g_p + (base + rowA) * 64;
            #pragma unroll
            for (int j = 0; j < 8; j++)
                *(float2*)(p + j * 8 + 2 * tig) = make_float2(acc2[j][0], acc2[j][1]);
        }
        if (rowB < NN) {
            float* p = g_p + (base + rowB) * 64;
            #pragma unroll
            for (int j = 0; j < 8; j++)
                *(float2*)(p + j * 8 + 2 * tig) = make_float2(acc2[j][2], acc2[j][3]);
        }
    }
}

// ---------------- launch ------------------------------------------------------
extern "C" void kernel_launch(void* const* d_in, const int* in_sizes, int n_in,
                              void* d_out, int out_size) {
    (void)in_sizes; (void)n_in; (void)out_size;
    const float* x   = (const float*)d_in[0];
    const float* ew  = (const float*)d_in[1];
    const float* W1  = (const float*)d_in[2];
    const float* W2  = (const float*)d_in[3];
    const float* m1  = (const float*)d_in[4];
    const float* m2  = (const float*)d_in[5];
    const int*   src = (const int*)d_in[6];
    const int*   dst = (const int*)d_in[7];
    float* out = (float*)d_out;

    cudaFuncSetAttribute((const void*)k_fused_gemm,
                         cudaFuncAttributeMaxDynamicSharedMemorySize, FUSED_SMEM);

    // 1. CSR build
    k_zero_counts<<<(NN + 255) / 256, 256>>>();
    k_hist<<<(EE + 255) / 256, 256>>>(dst);
    k_scan<<<1, 1024>>>();
    k_scatter<<<(EE + 255) / 256, 256>>>(src, dst, ew);

    // 2. agg1 = spmm(x)   [N x 96]
    k_spmm96<<<(NN * 32 + 255) / 256, 256>>>(x);

    // 3+4. fused tf32 mma: p_t = relu(agg1 @ (W1*m1_t)) @ (W2*m2_t)
    dim3 gf((NN + 127) / 128, TT);
    k_fused_gemm<<<gf, 256, FUSED_SMEM>>>(W1, W2, m1, m2);

    // 5. out_t = spmm(p_t)
    dim3 g3((NN * 32 + 255) / 256, TT);
    k_spmm64<<<g3, 256>>>(out);
}

// round 4
// speedup vs baseline: 2.2112x; 1.1293x over previous
#include <cuda_runtime.h>
#include <cuda_fp16.h>
#include <cstdint>

// Problem constants (fixed by the dataset)
#define NN    50000
#define EE    800000
#define IN_F  96
#define HID_F 128
#define OUT_F 64
#define TT    8

// ---------------- static device scratch (no allocations allowed) -------------
__device__ int      g_counts[NN];
__device__ int      g_rowptr[NN + 1];
__device__ int      g_cursor[NN];
__device__ int      g_csrc[EE];
__device__ float    g_cw[EE];
__device__ float    g_agg1[(size_t)NN * IN_F];              // 19.2 MB
__device__ __half   g_ph[(size_t)NN * TT * OUT_F];          // 51.2 MB, [n][t*64+c]
__device__ uint32_t g_B1[TT * IN_F * HID_F];                // tf32 W1*M1 per t
__device__ uint32_t g_B2[TT * HID_F * OUT_F];               // tf32 W2*M2 per t

// ---------------- helpers ------------------------------------------------------
__device__ __forceinline__ uint32_t f2tf32(float x) {
    uint32_t u;
    asm("cvt.rna.tf32.f32 %0, %1;" : "=r"(u) : "f"(x));
    return u;
}
__device__ __forceinline__ void mma_tf32(float d[4],
                                         uint32_t a0, uint32_t a1, uint32_t a2, uint32_t a3,
                                         uint32_t b0, uint32_t b1) {
    asm volatile("mma.sync.aligned.m16n8k8.row.col.f32.tf32.tf32.f32 "
        "{%0,%1,%2,%3}, {%4,%5,%6,%7}, {%8,%9}, {%0,%1,%2,%3};"
        : "+f"(d[0]), "+f"(d[1]), "+f"(d[2]), "+f"(d[3])
        : "r"(a0), "r"(a1), "r"(a2), "r"(a3), "r"(b0), "r"(b1));
}

// ---------------- CSR build --------------------------------------------------
__global__ void k_zero_counts() {
    int i = blockIdx.x * blockDim.x + threadIdx.x;
    if (i < NN) g_counts[i] = 0;
}
__global__ void k_hist(const int* __restrict__ dst) {
    int e = blockIdx.x * blockDim.x + threadIdx.x;
    if (e < EE) atomicAdd(&g_counts[dst[e]], 1);
}
__global__ void k_scan() {
    __shared__ int sums[1024];
    int tid = threadIdx.x;
    const int chunk = (NN + 1023) / 1024;
    int start = tid * chunk; if (start > NN) start = NN;
    int end   = start + chunk; if (end > NN) end = NN;
    int s = 0;
    for (int i = start; i < end; i++) s += g_counts[i];
    sums[tid] = s;
    __syncthreads();
    for (int off = 1; off < 1024; off <<= 1) {
        int v = (tid >= off) ? sums[tid - off] : 0;
        __syncthreads();
        sums[tid] += v;
        __syncthreads();
    }
    int run = (tid == 0) ? 0 : sums[tid - 1];
    for (int i = start; i < end; i++) {
        g_rowptr[i] = run;
        g_cursor[i] = run;
        run += g_counts[i];
    }
    if (end == NN) g_rowptr[NN] = run;
}
__global__ void k_scatter(const int* __restrict__ src, const int* __restrict__ dst,
                          const float* __restrict__ ew) {
    int e = blockIdx.x * blockDim.x + threadIdx.x;
    if (e >= EE) return;
    int d = dst[e];
    int pos = atomicAdd(&g_cursor[d], 1);
    g_csrc[pos] = src[e];
    g_cw[pos]   = ew[e];
}

// ---------------- weight prep: tf32(W .* M) for all t -------------------------
__global__ void k_prep(const float* __restrict__ W1, const float* __restrict__ W2,
                       const float* __restrict__ M1, const float* __restrict__ M2) {
    int i = blockIdx.x * blockDim.x + threadIdx.x;
    const int S1 = TT * IN_F * HID_F;          // 98304
    const int S2 = TT * HID_F * OUT_F;         // 65536
    if (i < S1) {
        int e = i % (IN_F * HID_F);
        g_B1[i] = f2tf32(W1[e] * M1[i]);
    } else if (i < S1 + S2) {
        int j = i - S1;
        int e = j % (HID_F * OUT_F);
        g_B2[j] = f2tf32(W2[e] * M2[j]);
    }
}

// ---------------- SpMM1: agg1 = spmm(x), warp per node, unroll 2 --------------
__global__ void k_spmm96(const float* __restrict__ x) {
    int warp = (blockIdx.x * blockDim.x + threadIdx.x) >> 5;
    int lane = threadIdx.x & 31;
    if (warp >= NN) return;
    int r0 = g_rowptr[warp], r1 = g_rowptr[warp + 1];
    float a0 = 0.f, a1 = 0.f, a2 = 0.f;
    int r = r0;
    for (; r + 1 < r1; r += 2) {
        int   s0 = g_csrc[r],   s1 = g_csrc[r + 1];
        float w0 = g_cw[r],     w1 = g_cw[r + 1];
        const float* f0 = x + (size_t)s0 * IN_F;
        const float* f1 = x + (size_t)s1 * IN_F;
        float v00 = f0[lane], v01 = f0[lane + 32], v02 = f0[lane + 64];
        float v10 = f1[lane], v11 = f1[lane + 32], v12 = f1[lane + 64];
        a0 += w0 * v00; a1 += w0 * v01; a2 += w0 * v02;
        a0 += w1 * v10; a1 += w1 * v11; a2 += w1 * v12;
    }
    if (r < r1) {
        int   s = g_csrc[r];
        float w = g_cw[r];
        const float* f = x + (size_t)s * IN_F;
        a0 += w * f[lane]; a1 += w * f[lane + 32]; a2 += w * f[lane + 64];
    }
    float* o = g_agg1 + (size_t)warp * IN_F;
    o[lane] = a0; o[lane + 32] = a1; o[lane + 64] = a2;
}

// ---------------- SpMM2: out[t,n,:] = spmm(p_t) for ALL t in one pass ---------
// warp per node; p row = 512 halves (1KB) contiguous; lane covers 16 channels.
__device__ __forceinline__ void acc8(float acc[16], int base, uint4 u, float w) {
    const __half2* h = (const __half2*)&u;
    #pragma unroll
    for (int q = 0; q < 4; q++) {
        float2 f = __half22float2(h[q]);
        acc[base + 2 * q]     += w * f.x;
        acc[base + 2 * q + 1] += w * f.y;
    }
}

__global__ void k_spmm_all(float* __restrict__ out) {
    int warp = (blockIdx.x * blockDim.x + threadIdx.x) >> 5;
    int lane = threadIdx.x & 31;
    if (warp >= NN) return;
    int r0 = g_rowptr[warp], r1 = g_rowptr[warp + 1];

    float acc[16];
    #pragma unroll
    for (int i = 0; i < 16; i++) acc[i] = 0.f;

    int r = r0;
    for (; r + 1 < r1; r += 2) {
        int   s0 = g_csrc[r],   s1 = g_csrc[r + 1];
        float w0 = g_cw[r],     w1 = g_cw[r + 1];
        const uint4* p0 = (const uint4*)(g_ph + (size_t)s0 * 512) + lane * 2;
        const uint4* p1 = (const uint4*)(g_ph + (size_t)s1 * 512) + lane * 2;
        uint4 u00 = p0[0], u01 = p0[1];
        uint4 u10 = p1[0], u11 = p1[1];
        acc8(acc, 0, u00, w0); acc8(acc, 8, u01, w0);
        acc8(acc, 0, u10, w1); acc8(acc, 8, u11, w1);
    }
    if (r < r1) {
        int   s = g_csrc[r];
        float w = g_cw[r];
        const uint4* p = (const uint4*)(g_ph + (size_t)s * 512) + lane * 2;
        uint4 u0 = p[0], u1 = p[1];
        acc8(acc, 0, u0, w); acc8(acc, 8, u1, w);
    }

    // lane covers channels [16*lane, 16*lane+16): t = lane/4, col0 = (lane%4)*16
    int t  = lane >> 2;
    int c0 = (lane & 3) * 16;
    float* op = out + ((size_t)t * NN + warp) * OUT_F + c0;
    #pragma unroll
    for (int q = 0; q < 4; q++)
        *(float4*)(op + q * 4) = make_float4(acc[q * 4], acc[q * 4 + 1],
                                             acc[q * 4 + 2], acc[q * 4 + 3]);
}

// ---------------- fused tf32 mma.sync GEMM (loop over all t per CTA) ----------
// smem words: A 128x96 lda=100 | B1 96x128 ldb1=136 | B2 128x64 ldb2=72 | H 128x128 ldh=132
#define OFF_A   0
#define LDA     100
#define OFF_B1  12800
#define LDB1    136
#define OFF_B2  25856
#define LDB2    72
#define OFF_H   35072
#define LDH     132
#define FUSED_WORDS (OFF_H + 128 * LDH)            // 51968 words
#define FUSED_SMEM  (FUSED_WORDS * 4)              // 207872 bytes

__global__ void __launch_bounds__(256, 1)
k_fused_gemm() {
    extern __shared__ uint32_t sm[];
    const int tid  = threadIdx.x;
    const int wid  = tid >> 5;
    const int lane = tid & 31;
    const int gid  = lane >> 2;      // 0..7
    const int tig  = lane & 3;       // 0..3
    const int row0 = blockIdx.x * 128;

    // ---- stage A tile ONCE (tf32), zero-fill OOB rows
    for (int e = tid; e < 128 * 96; e += 256) {
        int r = e / 96, k = e % 96;
        int gr = row0 + r;
        float v = (gr < NN) ? g_agg1[(size_t)gr * 96 + k] : 0.f;
        sm[OFF_A + r * LDA + k] = f2tf32(v);
    }

    const int r0 = wid * 16;
    const int rowA = row0 + r0 + gid;
    const int rowB = rowA + 8;

    for (int t = 0; t < TT; t++) {
        __syncthreads();   // previous GEMM2 reads done before restaging B
        // ---- stage prepared B1_t, B2_t (already tf32)
        {
            const uint32_t* b1 = g_B1 + (size_t)t * 96 * 128;
            for (int e = tid; e < 96 * 128; e += 256)
                sm[OFF_B1 + (e >> 7) * LDB1 + (e & 127)] = b1[e];
            const uint32_t* b2 = g_B2 + (size_t)t * 128 * 64;
            for (int e = tid; e < 128 * 64; e += 256)
                sm[OFF_B2 + (e >> 6) * LDB2 + (e & 63)] = b2[e];
        }
        __syncthreads();

        // ===== GEMM1: H[128,128] = A[128,96] @ B1 =====
        float acc1[16][4];
        #pragma unroll
        for (int j = 0; j < 16; j++)
            #pragma unroll
            for (int i = 0; i < 4; i++) acc1[j][i] = 0.f;

        #pragma unroll
        for (int kb = 0; kb < 12; kb++) {
            const int k0 = kb * 8;
            uint32_t a0 = sm[OFF_A + (r0 + gid)     * LDA + k0 + tig];
            uint32_t a1 = sm[OFF_A + (r0 + gid + 8) * LDA + k0 + tig];
            uint32_t a2 = sm[OFF_A + (r0 + gid)     * LDA + k0 + tig + 4];
            uint32_t a3 = sm[OFF_A + (r0 + gid + 8) * LDA + k0 + tig + 4];
            #pragma unroll
            for (int j = 0; j < 16; j++) {
                uint32_t b0 = sm[OFF_B1 + (k0 + tig)     * LDB1 + j * 8 + gid];
                uint32_t b1 = sm[OFF_B1 + (k0 + tig + 4) * LDB1 + j * 8 + gid];
                mma_tf32(acc1[j], a0, a1, a2, a3, b0, b1);
            }
        }

        // relu + tf32-round, store H (warp-private rows -> __syncwarp only)
        #pragma unroll
        for (int j = 0; j < 16; j++) {
            int cA = j * 8 + 2 * tig;
            float f0 = acc1[j][0], f1 = acc1[j][1], f2 = acc1[j][2], f3 = acc1[j][3];
            uint32_t u0 = f2tf32(f0 > 0.f ? f0 : 0.f);
            uint32_t u1 = f2tf32(f1 > 0.f ? f1 : 0.f);
            uint32_t u2 = f2tf32(f2 > 0.f ? f2 : 0.f);
            uint32_t u3 = f2tf32(f3 > 0.f ? f3 : 0.f);
            *(uint2*)&sm[OFF_H + (r0 + gid)     * LDH + cA] = make_uint2(u0, u1);
            *(uint2*)&sm[OFF_H + (r0 + gid + 8) * LDH + cA] = make_uint2(u2, u3);
        }
        __syncwarp();

        // ===== GEMM2: P[128,64] = H[128,128] @ B2 =====
        float acc2[8][4];
        #pragma unroll
        for (int j = 0; j < 8; j++)
            #pragma unroll
            for (int i = 0; i < 4; i++) acc2[j][i] = 0.f;

        #pragma unroll
        for (int kb = 0; kb < 16; kb++) {
            const int k0 = kb * 8;
            uint32_t a0 = sm[OFF_H + (r0 + gid)     * LDH + k0 + tig];
            uint32_t a1 = sm[OFF_H + (r0 + gid + 8) * LDH + k0 + tig];
            uint32_t a2 = sm[OFF_H + (r0 + gid)     * LDH + k0 + tig + 4];
            uint32_t a3 = sm[OFF_H + (r0 + gid + 8) * LDH + k0 + tig + 4];
            #pragma unroll
            for (int j = 0; j < 8; j++) {
                uint32_t b0 = sm[OFF_B2 + (k0 + tig)     * LDB2 + j * 8 + gid];
                uint32_t b1 = sm[OFF_B2 + (k0 + tig + 4) * LDB2 + j * 8 + gid];
                mma_tf32(acc2[j], a0, a1, a2, a3, b0, b1);
            }
        }

        // ---- epilogue: write p tile as fp16 into g_ph[n][t*64+c]
        if (rowA < NN) {
            __half* p = g_ph + (size_t)rowA * 512 + t * 64;
            #pragma unroll
            for (int j = 0; j < 8; j++)
                *(__half2*)(p + j * 8 + 2 * tig) =
                    __float22half2_rn(make_float2(acc2[j][0], acc2[j][1]));
        }
        if (rowB < NN) {
            __half* p = g_ph + (size_t)rowB * 512 + t * 64;
            #pragma unroll
            for (int j = 0; j < 8; j++)
                *(__half2*)(p + j * 8 + 2 * tig) =
                    __float22half2_rn(make_float2(acc2[j][2], acc2[j][3]));
        }
    }
}

// ---------------- launch ------------------------------------------------------
extern "C" void kernel_launch(void* const* d_in, const int* in_sizes, int n_in,
                              void* d_out, int out_size) {
    (void)in_sizes; (void)n_in; (void)out_size;
    const float* x   = (const float*)d_in[0];
    const float* ew  = (const float*)d_in[1];
    const float* W1  = (const float*)d_in[2];
    const float* W2  = (const float*)d_in[3];
    const float* m1  = (const float*)d_in[4];
    const float* m2  = (const float*)d_in[5];
    const int*   src = (const int*)d_in[6];
    const int*   dst = (const int*)d_in[7];
    float* out = (float*)d_out;

    cudaFuncSetAttribute((const void*)k_fused_gemm,
                         cudaFuncAttributeMaxDynamicSharedMemorySize, FUSED_SMEM);

    // 1. CSR build + weight prep
    k_zero_counts<<<(NN + 255) / 256, 256>>>();
    k_hist<<<(EE + 255) / 256, 256>>>(dst);
    k_scan<<<1, 1024>>>();
    k_scatter<<<(EE + 255) / 256, 256>>>(src, dst, ew);
    k_prep<<<(TT * (IN_F * HID_F + HID_F * OUT_F) + 255) / 256, 256>>>(W1, W2, m1, m2);

    // 2. agg1 = spmm(x)
    k_spmm96<<<(NN * 32 + 255) / 256, 256>>>(x);

    // 3+4. fused tf32 mma: p_t = relu(agg1 @ B1_t) @ B2_t, all t per CTA
    k_fused_gemm<<<(NN + 127) / 128, 256, FUSED_SMEM>>>();

    // 5. out = spmm(p) for all 8 samples in one pass
    k_spmm_all<<<(NN * 32 + 255) / 256, 256>>>(out);
}

// round 5
// speedup vs baseline: 2.6401x; 1.1940x over previous
#include <cuda_runtime.h>
#include <cuda_fp16.h>
#include <cstdint>

// Problem constants (fixed by the dataset)
#define NN    50000
#define EE    800000
#define IN_F  96
#define HID_F 128
#define OUT_F 64
#define TT    8

#define SCAN_BLK 512
#define NBLK ((NN + SCAN_BLK - 1) / SCAN_BLK)    // 98

// ---------------- static device scratch (no allocations allowed) -------------
__device__ int      g_counts[NN];
__device__ int      g_rowptr[NN + 1];
__device__ int      g_cursor[NN];
__device__ int      g_bsum[NBLK];
__device__ int      g_boff[NBLK];
__device__ int2     g_epack[EE];                            // (src, w-as-bits)
__device__ float    g_agg1[(size_t)NN * IN_F];              // 19.2 MB
__device__ __half   g_ph[(size_t)NN * TT * OUT_F];          // 51.2 MB, [n][t*64+c]
__device__ uint32_t g_B1[TT * IN_F * HID_F];                // tf32 W1*M1 per t
__device__ uint32_t g_B2[TT * HID_F * OUT_F];               // tf32 W2*M2 per t

// ---------------- helpers ------------------------------------------------------
__device__ __forceinline__ uint32_t f2tf32(float x) {
    uint32_t u;
    asm("cvt.rna.tf32.f32 %0, %1;" : "=r"(u) : "f"(x));
    return u;
}
__device__ __forceinline__ void mma_tf32(float d[4],
                                         uint32_t a0, uint32_t a1, uint32_t a2, uint32_t a3,
                                         uint32_t b0, uint32_t b1) {
    asm volatile("mma.sync.aligned.m16n8k8.row.col.f32.tf32.tf32.f32 "
        "{%0,%1,%2,%3}, {%4,%5,%6,%7}, {%8,%9}, {%0,%1,%2,%3};"
        : "+f"(d[0]), "+f"(d[1]), "+f"(d[2]), "+f"(d[3])
        : "r"(a0), "r"(a1), "r"(a2), "r"(a3), "r"(b0), "r"(b1));
}

// ---------------- CSR build --------------------------------------------------
__global__ void k_zero_counts() {
    int i = blockIdx.x * blockDim.x + threadIdx.x;
    if (i < NN) g_counts[i] = 0;
}
__global__ void k_hist(const int* __restrict__ dst) {
    int e = blockIdx.x * blockDim.x + threadIdx.x;
    if (e < EE) atomicAdd(&g_counts[dst[e]], 1);
}

// hierarchical scan: 98-block reduce -> 1-block scan of 98 -> 98-block local scan
__global__ void k_scan1() {
    __shared__ int s[SCAN_BLK];
    int b = blockIdx.x, tid = threadIdx.x;
    int i = b * SCAN_BLK + tid;
    s[tid] = (i < NN) ? g_counts[i] : 0;
    __syncthreads();
    #pragma unroll
    for (int off = SCAN_BLK / 2; off > 0; off >>= 1) {
        if (tid < off) s[tid] += s[tid + off];
        __syncthreads();
    }
    if (tid == 0) g_bsum[b] = s[0];
}
__global__ void k_scan2() {
    __shared__ int s[128];
    int tid = threadIdx.x;
    int v = (tid < NBLK) ? g_bsum[tid] : 0;
    s[tid] = v;
    __syncthreads();
    #pragma unroll
    for (int off = 1; off < 128; off <<= 1) {
        int u = (tid >= off) ? s[tid - off] : 0;
        __syncthreads();
        s[tid] += u;
        __syncthreads();
    }
    if (tid < NBLK) g_boff[tid] = s[tid] - v;
}
__global__ void k_scan3() {
    __shared__ int s[SCAN_BLK];
    int b = blockIdx.x, tid = threadIdx.x;
    int i = b * SCAN_BLK + tid;
    int c = (i < NN) ? g_counts[i] : 0;
    s[tid] = c;
    __syncthreads();
    #pragma unroll
    for (int off = 1; off < SCAN_BLK; off <<= 1) {
        int u = (tid >= off) ? s[tid - off] : 0;
        __syncthreads();
        s[tid] += u;
        __syncthreads();
    }
    if (i < NN) {
        int excl = s[tid] - c + g_boff[b];
        g_rowptr[i] = excl;
        g_cursor[i] = excl;
        if (i == NN - 1) g_rowptr[NN] = excl + c;
    }
}

__global__ void k_scatter(const int* __restrict__ src, const int* __restrict__ dst,
                          const float* __restrict__ ew) {
    int e = blockIdx.x * blockDim.x + threadIdx.x;
    if (e >= EE) return;
    int d = dst[e];
    int pos = atomicAdd(&g_cursor[d], 1);
    g_epack[pos] = make_int2(src[e], __float_as_int(ew[e]));
}

// ---------------- weight prep: tf32(W .* M) for all t -------------------------
__global__ void k_prep(const float* __restrict__ W1, const float* __restrict__ W2,
                       const float* __restrict__ M1, const float* __restrict__ M2) {
    int i = blockIdx.x * blockDim.x + threadIdx.x;
    const int S1 = TT * IN_F * HID_F;
    const int S2 = TT * HID_F * OUT_F;
    if (i < S1) {
        int e = i % (IN_F * HID_F);
        g_B1[i] = f2tf32(W1[e] * M1[i]);
    } else if (i < S1 + S2) {
        int j = i - S1;
        int e = j % (HID_F * OUT_F);
        g_B2[j] = f2tf32(W2[e] * M2[j]);
    }
}

// ---------------- SpMM1: agg1 = spmm(x), warp per node, unroll 4 --------------
__global__ void k_spmm96(const float* __restrict__ x) {
    int warp = (blockIdx.x * blockDim.x + threadIdx.x) >> 5;
    int lane = threadIdx.x & 31;
    if (warp >= NN) return;
    int r0 = g_rowptr[warp], r1 = g_rowptr[warp + 1];
    float a0 = 0.f, a1 = 0.f, a2 = 0.f;
    int r = r0;
    for (; r + 3 < r1; r += 4) {
        int2 e0 = g_epack[r],     e1 = g_epack[r + 1];
        int2 e2 = g_epack[r + 2], e3 = g_epack[r + 3];
        const float* f0 = x + (size_t)e0.x * IN_F;
        const float* f1 = x + (size_t)e1.x * IN_F;
        const float* f2 = x + (size_t)e2.x * IN_F;
        const float* f3 = x + (size_t)e3.x * IN_F;
        float v00 = f0[lane], v01 = f0[lane + 32], v02 = f0[lane + 64];
        float v10 = f1[lane], v11 = f1[lane + 32], v12 = f1[lane + 64];
        float v20 = f2[lane], v21 = f2[lane + 32], v22 = f2[lane + 64];
        float v30 = f3[lane], v31 = f3[lane + 32], v32 = f3[lane + 64];
        float w0 = __int_as_float(e0.y), w1 = __int_as_float(e1.y);
        float w2 = __int_as_float(e2.y), w3 = __int_as_float(e3.y);
        a0 += w0 * v00; a1 += w0 * v01; a2 += w0 * v02;
        a0 += w1 * v10; a1 += w1 * v11; a2 += w1 * v12;
        a0 += w2 * v20; a1 += w2 * v21; a2 += w2 * v22;
        a0 += w3 * v30; a1 += w3 * v31; a2 += w3 * v32;
    }
    for (; r < r1; r++) {
        int2 e = g_epack[r];
        float w = __int_as_float(e.y);
        const float* f = x + (size_t)e.x * IN_F;
        a0 += w * f[lane]; a1 += w * f[lane + 32]; a2 += w * f[lane + 64];
    }
    float* o = g_agg1 + (size_t)warp * IN_F;
    o[lane] = a0; o[lane + 32] = a1; o[lane + 64] = a2;
}

// ---------------- SpMM2: out[t,n,:] = spmm(p_t) for ALL t, unroll 4 -----------
__device__ __forceinline__ void acc8(float acc[16], int base, uint4 u, float w) {
    const __half2* h = (const __half2*)&u;
    #pragma unroll
    for (int q = 0; q < 4; q++) {
        float2 f = __half22float2(h[q]);
        acc[base + 2 * q]     += w * f.x;
        acc[base + 2 * q + 1] += w * f.y;
    }
}

__global__ void k_spmm_all(float* __restrict__ out) {
    int warp = (blockIdx.x * blockDim.x + threadIdx.x) >> 5;
    int lane = threadIdx.x & 31;
    if (warp >= NN) return;
    int r0 = g_rowptr[warp], r1 = g_rowptr[warp + 1];

    float acc[16];
    #pragma unroll
    for (int i = 0; i < 16; i++) acc[i] = 0.f;

    int r = r0;
    for (; r + 3 < r1; r += 4) {
        int2 e0 = g_epack[r],     e1 = g_epack[r + 1];
        int2 e2 = g_epack[r + 2], e3 = g_epack[r + 3];
        const uint4* p0 = (const uint4*)(g_ph + (size_t)e0.x * 512) + lane * 2;
        const uint4* p1 = (const uint4*)(g_ph + (size_t)e1.x * 512) + lane * 2;
        const uint4* p2 = (const uint4*)(g_ph + (size_t)e2.x * 512) + lane * 2;
        const uint4* p3 = (const uint4*)(g_ph + (size_t)e3.x * 512) + lane * 2;
        uint4 u00 = p0[0], u01 = p0[1];
        uint4 u10 = p1[0], u11 = p1[1];
        uint4 u20 = p2[0], u21 = p2[1];
        uint4 u30 = p3[0], u31 = p3[1];
        float w0 = __int_as_float(e0.y), w1 = __int_as_float(e1.y);
        float w2 = __int_as_float(e2.y), w3 = __int_as_float(e3.y);
        acc8(acc, 0, u00, w0); acc8(acc, 8, u01, w0);
        acc8(acc, 0, u10, w1); acc8(acc, 8, u11, w1);
        acc8(acc, 0, u20, w2); acc8(acc, 8, u21, w2);
        acc8(acc, 0, u30, w3); acc8(acc, 8, u31, w3);
    }
    for (; r < r1; r++) {
        int2 e = g_epack[r];
        float w = __int_as_float(e.y);
        const uint4* p = (const uint4*)(g_ph + (size_t)e.x * 512) + lane * 2;
        uint4 u0 = p[0], u1 = p[1];
        acc8(acc, 0, u0, w); acc8(acc, 8, u1, w);
    }

    int t  = lane >> 2;
    int c0 = (lane & 3) * 16;
    float* op = out + ((size_t)t * NN + warp) * OUT_F + c0;
    #pragma unroll
    for (int q = 0; q < 4; q++)
        *(float4*)(op + q * 4) = make_float4(acc[q * 4], acc[q * 4 + 1],
                                             acc[q * 4 + 2], acc[q * 4 + 3]);
}

// ---------------- fused tf32 mma.sync GEMM (loop over all t per CTA) ----------
#define OFF_A   0
#define LDA     100
#define OFF_B1  12800
#define LDB1    136
#define OFF_B2  25856
#define LDB2    72
#define OFF_H   35072
#define LDH     132
#define FUSED_WORDS (OFF_H + 128 * LDH)            // 51968 words
#define FUSED_SMEM  (FUSED_WORDS * 4)              // 207872 bytes

__global__ void __launch_bounds__(256, 1)
k_fused_gemm() {
    extern __shared__ uint32_t sm[];
    const int tid  = threadIdx.x;
    const int wid  = tid >> 5;
    const int lane = tid & 31;
    const int gid  = lane >> 2;
    const int tig  = lane & 3;
    const int row0 = blockIdx.x * 128;

    for (int e = tid; e < 128 * 96; e += 256) {
        int r = e / 96, k = e % 96;
        int gr = row0 + r;
        float v = (gr < NN) ? g_agg1[(size_t)gr * 96 + k] : 0.f;
        sm[OFF_A + r * LDA + k] = f2tf32(v);
    }

    const int r0 = wid * 16;
    const int rowA = row0 + r0 + gid;
    const int rowB = rowA + 8;

    for (int t = 0; t < TT; t++) {
        __syncthreads();
        {
            const uint32_t* b1 = g_B1 + (size_t)t * 96 * 128;
            for (int e = tid; e < 96 * 128; e += 256)
                sm[OFF_B1 + (e >> 7) * LDB1 + (e & 127)] = b1[e];
            const uint32_t* b2 = g_B2 + (size_t)t * 128 * 64;
            for (int e = tid; e < 128 * 64; e += 256)
                sm[OFF_B2 + (e >> 6) * LDB2 + (e & 63)] = b2[e];
        }
        __syncthreads();

        // ===== GEMM1: H[128,128] = A[128,96] @ B1 =====
        float acc1[16][4];
        #pragma unroll
        for (int j = 0; j < 16; j++)
            #pragma unroll
            for (int i = 0; i < 4; i++) acc1[j][i] = 0.f;

        #pragma unroll
        for (int kb = 0; kb < 12; kb++) {
            const int k0 = kb * 8;
            uint32_t a0 = sm[OFF_A + (r0 + gid)     * LDA + k0 + tig];
            uint32_t a1 = sm[OFF_A + (r0 + gid + 8) * LDA + k0 + tig];
            uint32_t a2 = sm[OFF_A + (r0 + gid)     * LDA + k0 + tig + 4];
            uint32_t a3 = sm[OFF_A + (r0 + gid + 8) * LDA + k0 + tig + 4];
            #pragma unroll
            for (int j = 0; j < 16; j++) {
                uint32_t b0 = sm[OFF_B1 + (k0 + tig)     * LDB1 + j * 8 + gid];
                uint32_t b1 = sm[OFF_B1 + (k0 + tig + 4) * LDB1 + j * 8 + gid];
                mma_tf32(acc1[j], a0, a1, a2, a3, b0, b1);
            }
        }

        #pragma unroll
        for (int j = 0; j < 16; j++) {
            int cA = j * 8 + 2 * tig;
            float f0 = acc1[j][0], f1 = acc1[j][1], f2 = acc1[j][2], f3 = acc1[j][3];
            uint32_t u0 = f2tf32(f0 > 0.f ? f0 : 0.f);
            uint32_t u1 = f2tf32(f1 > 0.f ? f1 : 0.f);
            uint32_t u2 = f2tf32(f2 > 0.f ? f2 : 0.f);
            uint32_t u3 = f2tf32(f3 > 0.f ? f3 : 0.f);
            *(uint2*)&sm[OFF_H + (r0 + gid)     * LDH + cA] = make_uint2(u0, u1);
            *(uint2*)&sm[OFF_H + (r0 + gid + 8) * LDH + cA] = make_uint2(u2, u3);
        }
        __syncwarp();

        // ===== GEMM2: P[128,64] = H[128,128] @ B2 =====
        float acc2[8][4];
        #pragma unroll
        for (int j = 0; j < 8; j++)
            #pragma unroll
            for (int i = 0; i < 4; i++) acc2[j][i] = 0.f;

        #pragma unroll
        for (int kb = 0; kb < 16; kb++) {
            const int k0 = kb * 8;
            uint32_t a0 = sm[OFF_H + (r0 + gid)     * LDH + k0 + tig];
            uint32_t a1 = sm[OFF_H + (r0 + gid + 8) * LDH + k0 + tig];
            uint32_t a2 = sm[OFF_H + (r0 + gid)     * LDH + k0 + tig + 4];
            uint32_t a3 = sm[OFF_H + (r0 + gid + 8) * LDH + k0 + tig + 4];
            #pragma unroll
            for (int j = 0; j < 8; j++) {
                uint32_t b0 = sm[OFF_B2 + (k0 + tig)     * LDB2 + j * 8 + gid];
                uint32_t b1 = sm[OFF_B2 + (k0 + tig + 4) * LDB2 + j * 8 + gid];
                mma_tf32(acc2[j], a0, a1, a2, a3, b0, b1);
            }
        }

        if (rowA < NN) {
            __half* p = g_ph + (size_t)rowA * 512 + t * 64;
            #pragma unroll
            for (int j = 0; j < 8; j++)
                *(__half2*)(p + j * 8 + 2 * tig) =
                    __float22half2_rn(make_float2(acc2[j][0], acc2[j][1]));
        }
        if (rowB < NN) {
            __half* p = g_ph + (size_t)rowB * 512 + t * 64;
            #pragma unroll
            for (int j = 0; j < 8; j++)
                *(__half2*)(p + j * 8 + 2 * tig) =
                    __float22half2_rn(make_float2(acc2[j][2], acc2[j][3]));
        }
    }
}

// ---------------- launch ------------------------------------------------------
extern "C" void kernel_launch(void* const* d_in, const int* in_sizes, int n_in,
                              void* d_out, int out_size) {
    (void)in_sizes; (void)n_in; (void)out_size;
    const float* x   = (const float*)d_in[0];
    const float* ew  = (const float*)d_in[1];
    const float* W1  = (const float*)d_in[2];
    const float* W2  = (const float*)d_in[3];
    const float* m1  = (const float*)d_in[4];
    const float* m2  = (const float*)d_in[5];
    const int*   src = (const int*)d_in[6];
    const int*   dst = (const int*)d_in[7];
    float* out = (float*)d_out;

    cudaFuncSetAttribute((const void*)k_fused_gemm,
                         cudaFuncAttributeMaxDynamicSharedMemorySize, FUSED_SMEM);

    // 1. CSR build (hierarchical scan) + weight prep
    k_zero_counts<<<(NN + 255) / 256, 256>>>();
    k_hist<<<(EE + 255) / 256, 256>>>(dst);
    k_scan1<<<NBLK, SCAN_BLK>>>();
    k_scan2<<<1, 128>>>();
    k_scan3<<<NBLK, SCAN_BLK>>>();
    k_scatter<<<(EE + 255) / 256, 256>>>(src, dst, ew);
    k_prep<<<(TT * (IN_F * HID_F + HID_F * OUT_F) + 255) / 256, 256>>>(W1, W2, m1, m2);

    // 2. agg1 = spmm(x)
    k_spmm96<<<(NN * 32 + 255) / 256, 256>>>(x);

    // 3+4. fused tf32 mma: p_t = relu(agg1 @ B1_t) @ B2_t
    k_fused_gemm<<<(NN + 127) / 128, 256, FUSED_SMEM>>>();

    // 5. out = spmm(p) for all 8 samples in one pass
    k_spmm_all<<<(NN * 32 + 255) / 256, 256>>>(out);
}

// round 6
// speedup vs baseline: 4.0865x; 1.5479x over previous
#include <cuda_runtime.h>
#include <cuda_fp16.h>
#include <cstdint>

// Problem constants (fixed by the dataset)
#define NN    50000
#define EE    800000
#define IN_F  96
#define HID_F 128
#define OUT_F 64
#define TT    8

#define SCAN_BLK 512
#define NBLK ((NN + SCAN_BLK - 1) / SCAN_BLK)    // 98

// ---------------- static device scratch (no allocations allowed) -------------
__device__ int      g_counts[NN];      // zero-init at load; re-zeroed by k_scan3
__device__ int      g_rowptr[NN + 1];
__device__ int      g_cursor[NN];
__device__ int      g_bsum[NBLK];
__device__ int      g_boff[NBLK];
__device__ int2     g_epack[EE];                            // (src, w-as-bits)
__device__ __half   g_xh[(size_t)NN * IN_F];                // 9.6 MB fp16 x
__device__ __half   g_agg1h[(size_t)NN * IN_F];             // 9.6 MB fp16 agg1
__device__ __half   g_ph[(size_t)NN * TT * OUT_F];          // 51.2 MB, [n][t*64+c]
__device__ uint32_t g_B1h[TT * HID_F * 48];                 // fp16x2 [t][n][k2], k2<48
__device__ uint32_t g_B2h[TT * OUT_F * 64];                 // fp16x2 [t][n][k2], k2<64

// ---------------- helpers ------------------------------------------------------
__device__ __forceinline__ void mma_f16(float d[4],
                                        uint32_t a0, uint32_t a1, uint32_t a2, uint32_t a3,
                                        uint32_t b0, uint32_t b1) {
    asm volatile("mma.sync.aligned.m16n8k16.row.col.f32.f16.f16.f32 "
        "{%0,%1,%2,%3}, {%4,%5,%6,%7}, {%8,%9}, {%0,%1,%2,%3};"
        : "+f"(d[0]), "+f"(d[1]), "+f"(d[2]), "+f"(d[3])
        : "r"(a0), "r"(a1), "r"(a2), "r"(a3), "r"(b0), "r"(b1));
}
__device__ __forceinline__ uint32_t pack_h2(float a, float b) {
    __half2 h = __float22half2_rn(make_float2(a, b));
    return *(uint32_t*)&h;
}

// ---------------- CSR build --------------------------------------------------
__global__ void k_hist(const int* __restrict__ dst) {
    int e = blockIdx.x * blockDim.x + threadIdx.x;
    if (e < EE) atomicAdd(&g_counts[dst[e]], 1);
}
__global__ void k_scan1() {
    __shared__ int s[SCAN_BLK];
    int b = blockIdx.x, tid = threadIdx.x;
    int i = b * SCAN_BLK + tid;
    s[tid] = (i < NN) ? g_counts[i] : 0;
    __syncthreads();
    #pragma unroll
    for (int off = SCAN_BLK / 2; off > 0; off >>= 1) {
        if (tid < off) s[tid] += s[tid + off];
        __syncthreads();
    }
    if (tid == 0) g_bsum[b] = s[0];
}
__global__ void k_scan2() {
    __shared__ int s[128];
    int tid = threadIdx.x;
    int v = (tid < NBLK) ? g_bsum[tid] : 0;
    s[tid] = v;
    __syncthreads();
    #pragma unroll
    for (int off = 1; off < 128; off <<= 1) {
        int u = (tid >= off) ? s[tid - off] : 0;
        __syncthreads();
        s[tid] += u;
        __syncthreads();
    }
    if (tid < NBLK) g_boff[tid] = s[tid] - v;
}
__global__ void k_scan3() {
    __shared__ int s[SCAN_BLK];
    int b = blockIdx.x, tid = threadIdx.x;
    int i = b * SCAN_BLK + tid;
    int c = (i < NN) ? g_counts[i] : 0;
    s[tid] = c;
    __syncthreads();
    #pragma unroll
    for (int off = 1; off < SCAN_BLK; off <<= 1) {
        int u = (tid >= off) ? s[tid - off] : 0;
        __syncthreads();
        s[tid] += u;
        __syncthreads();
    }
    if (i < NN) {
        int excl = s[tid] - c + g_boff[b];
        g_rowptr[i] = excl;
        g_cursor[i] = excl;
        g_counts[i] = 0;                      // restore invariant for next call
        if (i == NN - 1) g_rowptr[NN] = excl + c;
    }
}
__global__ void k_scatter(const int* __restrict__ src, const int* __restrict__ dst,
                          const float* __restrict__ ew) {
    int e = blockIdx.x * blockDim.x + threadIdx.x;
    if (e >= EE) return;
    int d = dst[e];
    int pos = atomicAdd(&g_cursor[d], 1);
    g_epack[pos] = make_int2(src[e], __float_as_int(ew[e]));
}

// ---------------- x -> fp16 conversion ----------------------------------------
__global__ void k_xhalf(const float* __restrict__ x) {
    int i = blockIdx.x * blockDim.x + threadIdx.x;      // half2 index
    if (i < NN * IN_F / 2) {
        float2 v = *(const float2*)(x + i * 2);
        *((__half2*)g_xh + i) = __float22half2_rn(v);
    }
}

// ---------------- weight prep: fp16x2 (W .* M), [t][n][k2] --------------------
__global__ void k_prep(const float* __restrict__ W1, const float* __restrict__ W2,
                       const float* __restrict__ M1, const float* __restrict__ M2) {
    int i = blockIdx.x * blockDim.x + threadIdx.x;
    const int S1 = TT * HID_F * 48;        // 49152
    const int S2 = TT * OUT_F * 64;        // 32768
    if (i < S1) {
        int t = i / (HID_F * 48);
        int rem = i % (HID_F * 48);
        int n = rem / 48, k2 = rem % 48;
        int e0 = (2 * k2) * HID_F + n;
        int e1 = e0 + HID_F;
        const float* m = M1 + (size_t)t * IN_F * HID_F;
        g_B1h[i] = pack_h2(W1[e0] * m[e0], W1[e1] * m[e1]);
    } else if (i < S1 + S2) {
        int j = i - S1;
        int t = j / (OUT_F * 64);
        int rem = j % (OUT_F * 64);
        int n = rem / 64, k2 = rem % 64;
        int e0 = (2 * k2) * OUT_F + n;
        int e1 = e0 + OUT_F;
        const float* m = M2 + (size_t)t * HID_F * OUT_F;
        g_B2h[j] = pack_h2(W2[e0] * m[e0], W2[e1] * m[e1]);
    }
}

// ---------------- SpMM1: agg1h = spmm(xh), warp per node, unroll 4 ------------
__global__ void k_spmm96() {
    int warp = (blockIdx.x * blockDim.x + threadIdx.x) >> 5;
    int lane = threadIdx.x & 31;
    if (warp >= NN) return;
    int r0 = g_rowptr[warp], r1 = g_rowptr[warp + 1];
    const uint32_t* xh = (const uint32_t*)g_xh;     // half2 granules, 48/row
    const bool hi = lane < 16;

    float2 A0 = make_float2(0.f, 0.f), A1 = make_float2(0.f, 0.f);
    int r = r0;
    for (; r + 3 < r1; r += 4) {
        int2 e0 = g_epack[r],     e1 = g_epack[r + 1];
        int2 e2 = g_epack[r + 2], e3 = g_epack[r + 3];
        uint32_t u00 = xh[e0.x * 48 + lane];
        uint32_t u10 = xh[e1.x * 48 + lane];
        uint32_t u20 = xh[e2.x * 48 + lane];
        uint32_t u30 = xh[e3.x * 48 + lane];
        uint32_t u01 = hi ? xh[e0.x * 48 + 32 + lane] : 0u;
        uint32_t u11 = hi ? xh[e1.x * 48 + 32 + lane] : 0u;
        uint32_t u21 = hi ? xh[e2.x * 48 + 32 + lane] : 0u;
        uint32_t u31 = hi ? xh[e3.x * 48 + 32 + lane] : 0u;
        float w0 = __int_as_float(e0.y), w1 = __int_as_float(e1.y);
        float w2 = __int_as_float(e2.y), w3 = __int_as_float(e3.y);
        float2 f;
        f = __half22float2(*(__half2*)&u00); A0.x += w0 * f.x; A0.y += w0 * f.y;
        f = __half22float2(*(__half2*)&u10); A0.x += w1 * f.x; A0.y += w1 * f.y;
        f = __half22float2(*(__half2*)&u20); A0.x += w2 * f.x; A0.y += w2 * f.y;
        f = __half22float2(*(__half2*)&u30); A0.x += w3 * f.x; A0.y += w3 * f.y;
        f = __half22float2(*(__half2*)&u01); A1.x += w0 * f.x; A1.y += w0 * f.y;
        f = __half22float2(*(__half2*)&u11); A1.x += w1 * f.x; A1.y += w1 * f.y;
        f = __half22float2(*(__half2*)&u21); A1.x += w2 * f.x; A1.y += w2 * f.y;
        f = __half22float2(*(__half2*)&u31); A1.x += w3 * f.x; A1.y += w3 * f.y;
    }
    for (; r < r1; r++) {
        int2 e = g_epack[r];
        float w = __int_as_float(e.y);
        uint32_t u0 = xh[e.x * 48 + lane];
        uint32_t u1 = hi ? xh[e.x * 48 + 32 + lane] : 0u;
        float2 f;
        f = __half22float2(*(__half2*)&u0); A0.x += w * f.x; A0.y += w * f.y;
        f = __half22float2(*(__half2*)&u1); A1.x += w * f.x; A1.y += w * f.y;
    }
    uint32_t* o = (uint32_t*)g_agg1h + (size_t)warp * 48;
    o[lane] = pack_h2(A0.x, A0.y);
    if (hi) o[32 + lane] = pack_h2(A1.x, A1.y);
}

// ---------------- SpMM2: out[t,n,:] = spmm(p_t) for ALL t, unroll 4 -----------
__device__ __forceinline__ void acc8(float acc[16], int base, uint4 u, float w) {
    const __half2* h = (const __half2*)&u;
    #pragma unroll
    for (int q = 0; q < 4; q++) {
        float2 f = __half22float2(h[q]);
        acc[base + 2 * q]     += w * f.x;
        acc[base + 2 * q + 1] += w * f.y;
    }
}

__global__ void k_spmm_all(float* __restrict__ out) {
    int warp = (blockIdx.x * blockDim.x + threadIdx.x) >> 5;
    int lane = threadIdx.x & 31;
    if (warp >= NN) return;
    int r0 = g_rowptr[warp], r1 = g_rowptr[warp + 1];

    float acc[16];
    #pragma unroll
    for (int i = 0; i < 16; i++) acc[i] = 0.f;

    int r = r0;
    for (; r + 3 < r1; r += 4) {
        int2 e0 = g_epack[r],     e1 = g_epack[r + 1];
        int2 e2 = g_epack[r + 2], e3 = g_epack[r + 3];
        const uint4* p0 = (const uint4*)(g_ph + (size_t)e0.x * 512) + lane * 2;
        const uint4* p1 = (const uint4*)(g_ph + (size_t)e1.x * 512) + lane * 2;
        const uint4* p2 = (const uint4*)(g_ph + (size_t)e2.x * 512) + lane * 2;
        const uint4* p3 = (const uint4*)(g_ph + (size_t)e3.x * 512) + lane * 2;
        uint4 u00 = p0[0], u01 = p0[1];
        uint4 u10 = p1[0], u11 = p1[1];
        uint4 u20 = p2[0], u21 = p2[1];
        uint4 u30 = p3[0], u31 = p3[1];
        float w0 = __int_as_float(e0.y), w1 = __int_as_float(e1.y);
        float w2 = __int_as_float(e2.y), w3 = __int_as_float(e3.y);
        acc8(acc, 0, u00, w0); acc8(acc, 8, u01, w0);
        acc8(acc, 0, u10, w1); acc8(acc, 8, u11, w1);
        acc8(acc, 0, u20, w2); acc8(acc, 8, u21, w2);
        acc8(acc, 0, u30, w3); acc8(acc, 8, u31, w3);
    }
    for (; r < r1; r++) {
        int2 e = g_epack[r];
        float w = __int_as_float(e.y);
        const uint4* p = (const uint4*)(g_ph + (size_t)e.x * 512) + lane * 2;
        uint4 u0 = p[0], u1 = p[1];
        acc8(acc, 0, u0, w); acc8(acc, 8, u1, w);
    }

    int t  = lane >> 2;
    int c0 = (lane & 3) * 16;
    float* op = out + ((size_t)t * NN + warp) * OUT_F + c0;
    #pragma unroll
    for (int q = 0; q < 4; q++)
        *(float4*)(op + q * 4) = make_float4(acc[q * 4], acc[q * 4 + 1],
                                             acc[q * 4 + 2], acc[q * 4 + 3]);
}

// ---------------- fused fp16 mma GEMM (loop over all t per CTA) ---------------
// smem uint32 (fp16x2) layout, padded lds for conflict-free fragment access:
//   A  128 rows x 48 k2, ld 52  @ 0       (6656)
//   B1 128 n    x 48 k2, ld 52  @ 6656    (6656)
//   B2 64  n    x 64 k2, ld 68  @ 13312   (4352)
//   H  128 rows x 64 k2, ld 68  @ 17664   (8704)
#define OFF_A   0
#define LDA     52
#define OFF_B1  6656
#define LDB1    52
#define OFF_B2  13312
#define LDB2    68
#define OFF_H   17664
#define LDH     68
#define FUSED_WORDS (OFF_H + 128 * LDH)            // 26368 words
#define FUSED_SMEM  (FUSED_WORDS * 4)              // 105472 bytes

__global__ void __launch_bounds__(256, 2)
k_fused_gemm() {
    extern __shared__ uint32_t sm[];
    const int tid  = threadIdx.x;
    const int wid  = tid >> 5;
    const int lane = tid & 31;
    const int gid  = lane >> 2;
    const int tig  = lane & 3;
    const int row0 = blockIdx.x * 128;

    // ---- stage A tile ONCE (fp16x2)
    const uint32_t* ah = (const uint32_t*)g_agg1h;
    for (int e = tid; e < 128 * 48; e += 256) {
        int r = e / 48, k2 = e % 48;
        int gr = row0 + r;
        sm[OFF_A + r * LDA + k2] = (gr < NN) ? ah[gr * 48 + k2] : 0u;
    }

    const int r0 = wid * 16;
    const int rowA = row0 + r0 + gid;
    const int rowB = rowA + 8;

    for (int t = 0; t < TT; t++) {
        __syncthreads();
        {
            const uint32_t* b1 = g_B1h + t * HID_F * 48;
            for (int e = tid; e < HID_F * 48; e += 256)
                sm[OFF_B1 + (e / 48) * LDB1 + (e % 48)] = b1[e];
            const uint32_t* b2 = g_B2h + t * OUT_F * 64;
            for (int e = tid; e < OUT_F * 64; e += 256)
                sm[OFF_B2 + (e >> 6) * LDB2 + (e & 63)] = b2[e];
        }
        __syncthreads();

        // ===== GEMM1: H[128,128] = A[128,96] @ B1, 6 k16-steps =====
        float acc1[16][4];
        #pragma unroll
        for (int j = 0; j < 16; j++)
            #pragma unroll
            for (int i = 0; i < 4; i++) acc1[j][i] = 0.f;

        #pragma unroll
        for (int kb = 0; kb < 6; kb++) {
            const int k2b = kb * 8;
            uint32_t a0 = sm[OFF_A + (r0 + gid)     * LDA + k2b + tig];
            uint32_t a1 = sm[OFF_A + (r0 + gid + 8) * LDA + k2b + tig];
            uint32_t a2 = sm[OFF_A + (r0 + gid)     * LDA + k2b + tig + 4];
            uint32_t a3 = sm[OFF_A + (r0 + gid + 8) * LDA + k2b + tig + 4];
            #pragma unroll
            for (int j = 0; j < 16; j++) {
                uint32_t b0 = sm[OFF_B1 + (j * 8 + gid) * LDB1 + k2b + tig];
                uint32_t b1 = sm[OFF_B1 + (j * 8 + gid) * LDB1 + k2b + tig + 4];
                mma_f16(acc1[j], a0, a1, a2, a3, b0, b1);
            }
        }

        // relu + fp16 pack, store H[row][k2] (warp-private rows)
        #pragma unroll
        for (int j = 0; j < 16; j++) {
            float f0 = acc1[j][0], f1 = acc1[j][1], f2 = acc1[j][2], f3 = acc1[j][3];
            uint32_t uA = pack_h2(f0 > 0.f ? f0 : 0.f, f1 > 0.f ? f1 : 0.f);
            uint32_t uB = pack_h2(f2 > 0.f ? f2 : 0.f, f3 > 0.f ? f3 : 0.f);
            sm[OFF_H + (r0 + gid)     * LDH + 4 * j + tig] = uA;
            sm[OFF_H + (r0 + gid + 8) * LDH + 4 * j + tig] = uB;
        }
        __syncwarp();

        // ===== GEMM2: P[128,64] = H[128,128] @ B2, 8 k16-steps =====
        float acc2[8][4];
        #pragma unroll
        for (int j = 0; j < 8; j++)
            #pragma unroll
            for (int i = 0; i < 4; i++) acc2[j][i] = 0.f;

        #pragma unroll
        for (int kb = 0; kb < 8; kb++) {
            const int k2b = kb * 8;
            uint32_t a0 = sm[OFF_H + (r0 + gid)     * LDH + k2b + tig];
            uint32_t a1 = sm[OFF_H + (r0 + gid + 8) * LDH + k2b + tig];
            uint32_t a2 = sm[OFF_H + (r0 + gid)     * LDH + k2b + tig + 4];
            uint32_t a3 = sm[OFF_H + (r0 + gid + 8) * LDH + k2b + tig + 4];
            #pragma unroll
            for (int j = 0; j < 8; j++) {
                uint32_t b0 = sm[OFF_B2 + (j * 8 + gid) * LDB2 + k2b + tig];
                uint32_t b1 = sm[OFF_B2 + (j * 8 + gid) * LDB2 + k2b + tig + 4];
                mma_f16(acc2[j], a0, a1, a2, a3, b0, b1);
            }
        }

        // ---- epilogue: write p tile as fp16 into g_ph[n][t*64+c]
        if (rowA < NN) {
            __half* p = g_ph + (size_t)rowA * 512 + t * 64;
            #pragma unroll
            for (int j = 0; j < 8; j++)
                *(uint32_t*)(p + j * 8 + 2 * tig) = pack_h2(acc2[j][0], acc2[j][1]);
        }
        if (rowB < NN) {
            __half* p = g_ph + (size_t)rowB * 512 + t * 64;
            #pragma unroll
            for (int j = 0; j < 8; j++)
                *(uint32_t*)(p + j * 8 + 2 * tig) = pack_h2(acc2[j][2], acc2[j][3]);
        }
    }
}

// ---------------- launch ------------------------------------------------------
extern "C" void kernel_launch(void* const* d_in, const int* in_sizes, int n_in,
                              void* d_out, int out_size) {
    (void)in_sizes; (void)n_in; (void)out_size;
    const float* x   = (const float*)d_in[0];
    const float* ew  = (const float*)d_in[1];
    const float* W1  = (const float*)d_in[2];
    const float* W2  = (const float*)d_in[3];
    const float* m1  = (const float*)d_in[4];
    const float* m2  = (const float*)d_in[5];
    const int*   src = (const int*)d_in[6];
    const int*   dst = (const int*)d_in[7];
    float* out = (float*)d_out;

    cudaFuncSetAttribute((const void*)k_fused_gemm,
                         cudaFuncAttributeMaxDynamicSharedMemorySize, FUSED_SMEM);

    // 1. CSR build (counts zeroed by previous call / load-time init)
    k_hist<<<(EE + 255) / 256, 256>>>(dst);
    k_scan1<<<NBLK, SCAN_BLK>>>();
    k_scan2<<<1, 128>>>();
    k_scan3<<<NBLK, SCAN_BLK>>>();
    k_scatter<<<(EE + 255) / 256, 256>>>(src, dst, ew);
    k_xhalf<<<(NN * IN_F / 2 + 255) / 256, 256>>>(x);
    k_prep<<<(TT * (HID_F * 48 + OUT_F * 64) + 255) / 256, 256>>>(W1, W2, m1, m2);

    // 2. agg1h = spmm(xh)
    k_spmm96<<<(NN * 32 + 255) / 256, 256>>>();

    // 3+4. fused fp16 mma: p_t = relu(agg1 @ B1_t) @ B2_t
    k_fused_gemm<<<(NN + 127) / 128, 256, FUSED_SMEM>>>();

    // 5. out = spmm(p) for all 8 samples in one pass
    k_spmm_all<<<(NN * 32 + 255) / 256, 256>>>(out);
}